// round 13
// baseline (speedup 1.0000x reference)
#include <cuda_runtime.h>

namespace {
constexpr int T_STEPS = 1000;
constexpr int B       = 256;
constexpr int IN_DIM  = 3;
constexpr int H       = 512;
constexpr int OUT_DIM = 2;
constexpr int NT      = 512;          // one thread per neuron
constexpr int NWARP   = NT / 32;      // 16
constexpr int TAIL    = 10;           // readout window
constexpr int SYNC_EVERY = 33;        // 30 * 33 == 990 == T_STEPS - TAIL (exact)
static_assert((T_STEPS - TAIL) % SYNC_EVERY == 0, "blocked loop must cover exactly 990 steps");
}

__global__ __launch_bounds__(NT)
void snn_fused_kernel(const float* __restrict__ x,
                      const float* __restrict__ W1,
                      const float* __restrict__ W2,
                      float* __restrict__ out,
                      long long avg_off)
{
    __shared__ float4 xs[T_STEPS];              // 16 KB: this batch element's inputs, padded
    __shared__ float  tailbuf[TAIL][2][NWARP];  // per-t, per-warp partial W2 dots
    __shared__ float  sg[2][TAIL];              // per-t sigmoid values

    const int b   = blockIdx.x;
    const int tid = threadIdx.x;

    // Stage the whole input sequence for this b into smem (2 iters/thread).
    for (int t = tid; t < T_STEPS; t += NT) {
        const float* xp = x + ((size_t)t * B + b) * IN_DIM;
        xs[t] = make_float4(xp[0], xp[1], xp[2], 0.0f);
    }

    // This thread's neuron weights
    const int h = tid;
    const float w10 = W1[(size_t)h * IN_DIM + 0];
    const float w11 = W1[(size_t)h * IN_DIM + 1];
    const float w12 = W1[(size_t)h * IN_DIM + 2];
    const float w2r0 = W2[h];        // W2[0, h]
    const float w2r1 = W2[H + h];    // W2[1, h]

    __syncthreads();

    float mem = 0.0f;
    bool  p   = false;               // reset predicate = (mem_prev > 1) = previous spike
    float* outp = out + (size_t)b * H + h;

    // ---- main recurrence: exactly 990 steps in 30 blocks of 33 ----
    for (int tb = 0; tb < T_STEPS - TAIL; tb += SYNC_EVERY) {
#pragma unroll 11
        for (int t = tb; t < tb + SYNC_EVERY; ++t) {
            const float4 xv = xs[t];
            // cur = x0*w0 (+fma) x1*w1 (+fma) x2*w2  (k-ascending fma chain)
            float cur = __fmaf_rn(xv.z, w12,
                        __fmaf_rn(xv.y, w11,
                        __fmul_rn(xv.x, w10)));
            // mem_new = (0.8*mem + cur) * (1 - reset), reset from PREVIOUS mem (== prev spike)
            float vm = __fadd_rn(__fmul_rn(0.8f, mem), cur);
            float mn = p ? 0.0f : vm;
            p   = (mn > 1.0f);                 // spike AND next step's reset
            mem = mn;
            __stwt(outp, p ? 1.0f : 0.0f);     // write-through: never read, no L2 dirty debt
            outp += B * H;
        }
        __syncthreads();   // bound warp drift -> concurrent stores cluster in few t-slices
    }

    // ---- last 10 steps: recurrence + barrier-free partial recording ----
    const int lane = tid & 31;
    const int warp = tid >> 5;
#pragma unroll
    for (int ti = 0; ti < TAIL; ++ti) {
        const int t = T_STEPS - TAIL + ti;
        const float4 xv = xs[t];
        float cur = __fmaf_rn(xv.z, w12,
                    __fmaf_rn(xv.y, w11,
                    __fmul_rn(xv.x, w10)));
        float vm = __fadd_rn(__fmul_rn(0.8f, mem), cur);
        float mn = p ? 0.0f : vm;
        p   = (mn > 1.0f);
        mem = mn;
        float s = p ? 1.0f : 0.0f;
        __stwt(outp, s);
        outp += B * H;

        float p0 = s * w2r0;
        float p1 = s * w2r1;
#pragma unroll
        for (int off = 16; off > 0; off >>= 1) {
            p0 += __shfl_down_sync(0xffffffffu, p0, off);
            p1 += __shfl_down_sync(0xffffffffu, p1, off);
        }
        if (lane == 0) { tailbuf[ti][0][warp] = p0; tailbuf[ti][1][warp] = p1; }
    }
    __syncthreads();   // all tail partials recorded

    // threads 0..9 each reduce one timestep and apply sigmoid
    if (tid < TAIL) {
        float d0 = 0.0f, d1 = 0.0f;
#pragma unroll
        for (int w = 0; w < NWARP; ++w) { d0 += tailbuf[tid][0][w]; d1 += tailbuf[tid][1][w]; }
        sg[0][tid] = 1.0f / (1.0f + expf(-d0));
        sg[1][tid] = 1.0f / (1.0f + expf(-d1));
    }
    __syncthreads();

    if (tid == 0) {
        float a0 = 0.0f, a1 = 0.0f;
#pragma unroll
        for (int ti = 0; ti < TAIL; ++ti) { a0 += sg[0][ti]; a1 += sg[1][ti]; }
        float* ao = out + avg_off + (size_t)b * OUT_DIM;
        ao[0] = a0 * 0.1f;
        ao[1] = a1 * 0.1f;
    }
}

extern "C" void kernel_launch(void* const* d_in, const int* in_sizes, int n_in,
                              void* d_out, int out_size) {
    const float* x  = (const float*)d_in[0];   // x_seq [1000, 256, 3]
    const float* W1 = (const float*)d_in[1];   // [512, 3]
    const float* W2 = (const float*)d_in[2];   // [2, 512]
    float* out = (float*)d_out;
    long long avg_off = (long long)out_size - (long long)(B * OUT_DIM);
    snn_fused_kernel<<<B, NT>>>(x, W1, W2, out, avg_off);
}

// round 14
// speedup vs baseline: 1.4367x; 1.4367x over previous
#include <cuda_runtime.h>

namespace {
constexpr int T_STEPS = 1000;
constexpr int B       = 256;
constexpr int IN_DIM  = 3;
constexpr int H       = 512;
constexpr int OUT_DIM = 2;
constexpr int NT      = 512;          // one thread per neuron
constexpr int NWARP   = NT / 32;      // 16
constexpr int TAIL    = 10;           // readout window
}

__global__ __launch_bounds__(NT)
void snn_fused_kernel(const float* __restrict__ x,
                      const float* __restrict__ W1,
                      const float* __restrict__ W2,
                      float* __restrict__ out,
                      long long avg_off)
{
    __shared__ float4 xs[T_STEPS];              // 16 KB: this batch element's inputs, padded
    __shared__ float  tailbuf[TAIL][2][NWARP];  // per-t, per-warp partial W2 dots
    __shared__ float  sg[2][TAIL];              // per-t sigmoid values

    const int b   = blockIdx.x;
    const int tid = threadIdx.x;

    // Stage the whole input sequence for this b into smem (2 iters/thread).
    for (int t = tid; t < T_STEPS; t += NT) {
        const float* xp = x + ((size_t)t * B + b) * IN_DIM;
        xs[t] = make_float4(xp[0], xp[1], xp[2], 0.0f);
    }

    // This thread's neuron weights
    const int h = tid;
    const float w10 = W1[(size_t)h * IN_DIM + 0];
    const float w11 = W1[(size_t)h * IN_DIM + 1];
    const float w12 = W1[(size_t)h * IN_DIM + 2];
    const float w2r0 = W2[h];        // W2[0, h]
    const float w2r1 = W2[H + h];    // W2[1, h]

    __syncthreads();

    float mem = 0.0f;
    bool  p   = false;               // reset predicate = (mem_prev > 1) = previous spike
    float* outp = out + (size_t)b * H + h;

    // ---- main recurrence: 990 steps, NO barriers — let warps drift so
    //      concurrent stores spread across many t-slices (bank parallelism) ----
#pragma unroll 10
    for (int t = 0; t < T_STEPS - TAIL; ++t) {
        const float4 xv = xs[t];
        // cur = x0*w0 (+fma) x1*w1 (+fma) x2*w2  (k-ascending fma chain)
        float cur = __fmaf_rn(xv.z, w12,
                    __fmaf_rn(xv.y, w11,
                    __fmul_rn(xv.x, w10)));
        // mem_new = (0.8*mem + cur) * (1 - reset), reset from PREVIOUS mem (== prev spike)
        float vm = __fadd_rn(__fmul_rn(0.8f, mem), cur);
        float mn = p ? 0.0f : vm;
        p   = (mn > 1.0f);                 // spike AND next step's reset
        mem = mn;
        __stwt(outp, p ? 1.0f : 0.0f);     // write-through: never read, no L2 dirty debt
        outp += B * H;
    }

    // ---- last 10 steps: recurrence + barrier-free partial recording ----
    const int lane = tid & 31;
    const int warp = tid >> 5;
#pragma unroll
    for (int ti = 0; ti < TAIL; ++ti) {
        const int t = T_STEPS - TAIL + ti;
        const float4 xv = xs[t];
        float cur = __fmaf_rn(xv.z, w12,
                    __fmaf_rn(xv.y, w11,
                    __fmul_rn(xv.x, w10)));
        float vm = __fadd_rn(__fmul_rn(0.8f, mem), cur);
        float mn = p ? 0.0f : vm;
        p   = (mn > 1.0f);
        mem = mn;
        float s = p ? 1.0f : 0.0f;
        __stwt(outp, s);
        outp += B * H;

        float p0 = s * w2r0;
        float p1 = s * w2r1;
#pragma unroll
        for (int off = 16; off > 0; off >>= 1) {
            p0 += __shfl_down_sync(0xffffffffu, p0, off);
            p1 += __shfl_down_sync(0xffffffffu, p1, off);
        }
        if (lane == 0) { tailbuf[ti][0][warp] = p0; tailbuf[ti][1][warp] = p1; }
    }
    __syncthreads();   // all tail partials recorded

    // threads 0..9 each reduce one timestep and apply sigmoid
    if (tid < TAIL) {
        float d0 = 0.0f, d1 = 0.0f;
#pragma unroll
        for (int w = 0; w < NWARP; ++w) { d0 += tailbuf[tid][0][w]; d1 += tailbuf[tid][1][w]; }
        sg[0][tid] = 1.0f / (1.0f + expf(-d0));
        sg[1][tid] = 1.0f / (1.0f + expf(-d1));
    }
    __syncthreads();

    if (tid == 0) {
        float a0 = 0.0f, a1 = 0.0f;
#pragma unroll
        for (int ti = 0; ti < TAIL; ++ti) { a0 += sg[0][ti]; a1 += sg[1][ti]; }
        float* ao = out + avg_off + (size_t)b * OUT_DIM;
        ao[0] = a0 * 0.1f;
        ao[1] = a1 * 0.1f;
    }
}

extern "C" void kernel_launch(void* const* d_in, const int* in_sizes, int n_in,
                              void* d_out, int out_size) {
    const float* x  = (const float*)d_in[0];   // x_seq [1000, 256, 3]
    const float* W1 = (const float*)d_in[1];   // [512, 3]
    const float* W2 = (const float*)d_in[2];   // [2, 512]
    float* out = (float*)d_out;
    long long avg_off = (long long)out_size - (long long)(B * OUT_DIM);
    snn_fused_kernel<<<B, NT>>>(x, W1, W2, out, avg_off);
}